// round 6
// baseline (speedup 1.0000x reference)
#include <cuda_runtime.h>
#include <math.h>

#define J    23
#define TPB  256
#define VPB  512
#define PI_F 3.14159265358979323846f

__constant__ int cPAR[J] = {-1,0,1,1,3,4,5,4,7,4,9,1,11,12,13,12,15,12,17,0,19,0,21};

static __device__ float4 g_A[J * 3];
static __device__ float  g_const[4];

// ---- packed f32x2 helpers (sm_103a FFMA2 path is PTX-only) ----
__device__ __forceinline__ void fma2(unsigned long long& d,
                                     unsigned long long a,
                                     unsigned long long b) {
    asm("fma.rn.f32x2 %0, %1, %2, %0;" : "+l"(d) : "l"(a), "l"(b));
}
__device__ __forceinline__ unsigned long long pack2(float v) {
    unsigned long long r;
    asm("mov.b64 %0, {%1, %1};" : "=l"(r) : "f"(v));
    return r;
}
__device__ __forceinline__ void unpack2(unsigned long long v, float& lo, float& hi) {
    asm("mov.b64 {%0, %1}, %2;" : "=f"(lo), "=f"(hi) : "l"(v));
}

// ---------------- Prep: one warp. pose -> Rodrigues -> FK -> A + small outputs ----------------
__global__ void __launch_bounds__(32) prep_kernel(
    const float* __restrict__ jr,
    const float* __restrict__ p0, const float* __restrict__ p1,
    const float* __restrict__ p2, const float* __restrict__ p3,
    const float* __restrict__ p4, const float* __restrict__ p5,
    const float* __restrict__ p12, const float* __restrict__ p13,
    const float* __restrict__ disp, const float* __restrict__ scale,
    const float* __restrict__ loc,
    float* __restrict__ out, int B, int V)
{
    __shared__ float s_Tl[J * 12];
    __shared__ float s_G[J * 12];
    __shared__ float s_pose[J * 3];

    const int tid = threadIdx.x;

    float cst = 0.f, ox = 0.f, oy = 0.f, oz = 0.f;
    if (tid == 31) {
        cst = 0.0035f * scale[0];
        ox = loc[0] + 0.1f * tanhf(disp[0]);
        oy = loc[1] + 0.1f * tanhf(disp[1]);
        oz = loc[2] + 0.1f * tanhf(disp[2]);
        g_const[0] = cst; g_const[1] = ox; g_const[2] = oy; g_const[3] = oz;
    }

    if (tid < J) {
        float fac = 0.f, sy = 1.f, sz = 1.f;
        const float* pp = p0;
        bool has = true;
        switch (tid) {
            case 0:  fac = PI_F / 2.f; pp = p0;  break;
            case 1:  fac = PI_F / 4.f; pp = p1;  break;
            case 2:  fac = PI_F / 9.f; pp = p2;  break;
            case 3:  fac = PI_F / 3.f; pp = p3;  break;
            case 4:  fac = PI_F / 3.f; pp = p4;  break;
            case 5:  fac = PI_F / 3.f; pp = p5;  break;
            case 11: fac = PI_F / 3.f; pp = p3;  sy = -1.f; sz = -1.f; break;
            case 12: fac = PI_F / 3.f; pp = p12; break;
            case 13: fac = PI_F / 3.f; pp = p13; break;
            default: has = false;
        }
        float px = 0.f, py = 0.f, pz = 0.f;
        if (has) {
            px = fac * tanhf(pp[0]);
            py = sy * fac * tanhf(pp[1]);
            pz = sz * fac * tanhf(pp[2]);
        }
        s_pose[3 * tid + 0] = px;
        s_pose[3 * tid + 1] = py;
        s_pose[3 * tid + 2] = pz;

        float ang = sqrtf(px * px + py * py + pz * pz + 1e-12f);
        float inv = 1.f / ang;
        float x = px * inv, y = py * inv, z = pz * inv;
        float s = sinf(ang), c = cosf(ang), t = 1.f - c;
        float* T = &s_Tl[tid * 12];
        T[0] = 1.f + t * (-(z * z) - (y * y));
        T[1] = -s * z + t * (x * y);
        T[2] =  s * y + t * (x * z);
        T[4] =  s * z + t * (x * y);
        T[5] = 1.f + t * (-(z * z) - (x * x));
        T[6] = -s * x + t * (y * z);
        T[8] = -s * y + t * (x * z);
        T[9] =  s * x + t * (y * z);
        T[10] = 1.f + t * (-(y * y) - (x * x));

        int par = cPAR[tid];
        float jx = jr[3 * tid], jy = jr[3 * tid + 1], jz = jr[3 * tid + 2];
        if (par >= 0) { jx -= jr[3 * par]; jy -= jr[3 * par + 1]; jz -= jr[3 * par + 2]; }
        T[3] = jx; T[7] = jy; T[11] = jz;
    }
    __syncwarp();

    if (tid < 12) s_G[tid] = s_Tl[tid];
    __syncwarp();
    #pragma unroll
    for (int j = 1; j < J; j++) {
        const int p = cPAR[j];
        if (tid < 12) {
            const int r = tid >> 2, c = tid & 3;
            const float* gp = &s_G[p * 12 + r * 4];
            const float* tl = &s_Tl[j * 12];
            float v = gp[0] * tl[0 * 4 + c]
                    + gp[1] * tl[1 * 4 + c]
                    + gp[2] * tl[2 * 4 + c];
            if (c == 3) v += gp[3];
            s_G[j * 12 + tid] = v;
        }
        __syncwarp();
    }

    if (tid < J) {
        const float* g = &s_G[tid * 12];
        float jx = jr[3 * tid], jy = jr[3 * tid + 1], jz = jr[3 * tid + 2];
        float tcx = g[0] * jx + g[1] * jy + g[2] * jz;
        float tcy = g[4] * jx + g[5] * jy + g[6] * jz;
        float tcz = g[8] * jx + g[9] * jy + g[10] * jz;
        g_A[tid * 3 + 0] = make_float4(g[0], g[1], g[2],  g[3]  - tcx);
        g_A[tid * 3 + 1] = make_float4(g[4], g[5], g[6],  g[7]  - tcy);
        g_A[tid * 3 + 2] = make_float4(g[8], g[9], g[10], g[11] - tcz);
    }

    const long V3 = 3L * (long)V;
    const long base = (long)B * V3;
    if (tid < J) {
        out[base + 3 * tid + 0] = s_pose[3 * tid + 0];
        out[base + 3 * tid + 1] = s_pose[3 * tid + 1];
        out[base + 3 * tid + 2] = s_pose[3 * tid + 2];
    }
    __syncwarp();
    if (tid == 31) {
        for (int j = 0; j < J; j++) {
            out[base + 69 + 3 * j + 0] = fmaf(cst, s_G[j * 12 + 3],  ox);
            out[base + 69 + 3 * j + 1] = fmaf(cst, s_G[j * 12 + 7],  oy);
            out[base + 69 + 3 * j + 2] = fmaf(cst, s_G[j * 12 + 11], oz);
        }
        out[base + 138] = scale[0];
        out[base + 139] = disp[0];
        out[base + 140] = disp[1];
        out[base + 141] = disp[2];
    }
}

// Dynamic smem layout (floats):
//   [0, 11776)        s_sk  (512*23)
//   [11776, 13312)    s_res (512*3)
//   [13312, 13588)    s_A   (69 float4 = 276 floats)
//   [13588, 13592)    s_c
#define SM_SK   0
#define SM_RES  11776
#define SM_A    13312
#define SM_C    13588
#define SMEM_FLOATS 13592
#define SMEM_BYTES  (SMEM_FLOATS * 4)

__global__ void __launch_bounds__(TPB, 3) lbs_kernel(
    const float* __restrict__ vt,
    const float* __restrict__ sk,
    const float* __restrict__ la,
    float* __restrict__ out, int V, int B)
{
    extern __shared__ float smem[];
    float* s_sk  = smem + SM_SK;
    float* s_res = smem + SM_RES;
    float* s_A   = smem + SM_A;
    float* s_c   = smem + SM_C;

    const int tid = threadIdx.x;
    const long v0 = (long)blockIdx.x * VPB;
    const int nv  = (V - (int)v0 < VPB) ? (V - (int)v0) : VPB;
    const long V3 = 3L * (long)V;
    const long offLa = (long)B * V3 + 142;

    // A + consts into smem
    if (tid < J * 3) ((float4*)s_A)[tid] = g_A[tid];
    if (tid >= 96 && tid < 100) s_c[tid - 96] = g_const[tid - 96];

    // cooperative coalesced sk tile load
    {
        const float4* g4 = (const float4*)(sk + v0 * 23);
        float4* d4 = (float4*)s_sk;
        const int nS = (nv * 23 + 3) >> 2;
        #pragma unroll 4
        for (int i = tid; i < nS; i += TPB) d4[i] = __ldcs(g4 + i);
    }

    // per-thread direct scalar loads for both halves + la passthrough + vh
    const bool actA = (tid < nv);
    const bool actB = (tid + 256 < nv);
    float vhA[3], vhB[3];
    {
        const long vA = v0 + tid;
        const long vB = v0 + tid + 256;
        if (actA) {
            #pragma unroll
            for (int k = 0; k < 3; k++) {
                float l = __ldcs(la + 3 * vA + k);
                __stcs(out + offLa + 3 * vA + k, l);
                vhA[k] = __ldcs(vt + 3 * vA + k) + 0.1f * tanhf(l);
            }
        }
        if (actB) {
            #pragma unroll
            for (int k = 0; k < 3; k++) {
                float l = __ldcs(la + 3 * vB + k);
                __stcs(out + offLa + 3 * vB + k, l);
                vhB[k] = __ldcs(vt + 3 * vB + k) + 0.1f * tanhf(l);
            }
        }
    }
    __syncthreads();

    // ---- main accumulation: T = sum_j w_j A_j, packed f32x2, 2 vertices ----
    unsigned long long accA[6] = {0, 0, 0, 0, 0, 0};
    unsigned long long accB[6] = {0, 0, 0, 0, 0, 0};
    {
        const float* wA = s_sk + 23 * tid;
        const float* wB = wA + 23 * 256;
        const unsigned long long* A2 = (const unsigned long long*)s_A;  // 6 u64 per joint
        #pragma unroll
        for (int j = 0; j < J; j++) {
            const unsigned long long a0 = A2[6 * j + 0];
            const unsigned long long a1 = A2[6 * j + 1];
            const unsigned long long a2 = A2[6 * j + 2];
            const unsigned long long a3 = A2[6 * j + 3];
            const unsigned long long a4 = A2[6 * j + 4];
            const unsigned long long a5 = A2[6 * j + 5];
            const unsigned long long wa = pack2(wA[j]);
            const unsigned long long wb = pack2(wB[j]);
            fma2(accA[0], wa, a0); fma2(accA[1], wa, a1);
            fma2(accA[2], wa, a2); fma2(accA[3], wa, a3);
            fma2(accA[4], wa, a4); fma2(accA[5], wa, a5);
            fma2(accB[0], wb, a0); fma2(accB[1], wb, a1);
            fma2(accB[2], wb, a2); fma2(accB[3], wb, a3);
            fma2(accB[4], wb, a4); fma2(accB[5], wb, a5);
        }
    }

    // ---- epilogue: apply transform, scale/offset, stage to s_res ----
    {
        const float c = s_c[0], o1 = s_c[1], o2 = s_c[2], o3 = s_c[3];

        float T0x,T0y,T0z,T0w,T1x,T1y,T1z,T1w,T2x,T2y,T2z,T2w;
        unpack2(accA[0], T0x, T0y); unpack2(accA[1], T0z, T0w);
        unpack2(accA[2], T1x, T1y); unpack2(accA[3], T1z, T1w);
        unpack2(accA[4], T2x, T2y); unpack2(accA[5], T2z, T2w);
        {
            float x = fmaf(T0x, vhA[0], fmaf(T0y, vhA[1], fmaf(T0z, vhA[2], T0w)));
            float y = fmaf(T1x, vhA[0], fmaf(T1y, vhA[1], fmaf(T1z, vhA[2], T1w)));
            float z = fmaf(T2x, vhA[0], fmaf(T2y, vhA[1], fmaf(T2z, vhA[2], T2w)));
            if (actA) {
                s_res[3 * tid + 0] = fmaf(c, x, o1);
                s_res[3 * tid + 1] = fmaf(c, y, o2);
                s_res[3 * tid + 2] = fmaf(c, z, o3);
            }
        }
        unpack2(accB[0], T0x, T0y); unpack2(accB[1], T0z, T0w);
        unpack2(accB[2], T1x, T1y); unpack2(accB[3], T1z, T1w);
        unpack2(accB[4], T2x, T2y); unpack2(accB[5], T2z, T2w);
        {
            float x = fmaf(T0x, vhB[0], fmaf(T0y, vhB[1], fmaf(T0z, vhB[2], T0w)));
            float y = fmaf(T1x, vhB[0], fmaf(T1y, vhB[1], fmaf(T1z, vhB[2], T1w)));
            float z = fmaf(T2x, vhB[0], fmaf(T2y, vhB[1], fmaf(T2z, vhB[2], T2w)));
            if (actB) {
                s_res[3 * (tid + 256) + 0] = fmaf(c, x, o1);
                s_res[3 * (tid + 256) + 1] = fmaf(c, y, o2);
                s_res[3 * (tid + 256) + 2] = fmaf(c, z, o3);
            }
        }
    }
    __syncthreads();

    // ---- coalesced batch stores ----
    {
        const int nf = nv * 3;
        const int n4 = nf >> 2;
        const float4* r4 = (const float4*)s_res;
        for (int b = 0; b < B; b++) {
            float* ob = out + (long)b * V3 + v0 * 3;
            float4* go = (float4*)ob;
            for (int i = tid; i < n4; i += TPB) __stcs(go + i, r4[i]);
            for (int i = (n4 << 2) + tid; i < nf; i += TPB) ob[i] = s_res[i];
        }
    }
}

extern "C" void kernel_launch(void* const* d_in, const int* in_sizes, int n_in,
                              void* d_out, int out_size)
{
    const float* vt    = (const float*)d_in[0];
    const float* sk    = (const float*)d_in[1];
    const float* jr    = (const float*)d_in[2];
    const float* p0    = (const float*)d_in[3];
    const float* p1    = (const float*)d_in[4];
    const float* p2    = (const float*)d_in[5];
    const float* p3    = (const float*)d_in[6];
    const float* p4    = (const float*)d_in[7];
    const float* p5    = (const float*)d_in[8];
    const float* p12   = (const float*)d_in[9];
    const float* p13   = (const float*)d_in[10];
    const float* la    = (const float*)d_in[11];
    const float* disp  = (const float*)d_in[12];
    const float* scale = (const float*)d_in[13];
    const float* loc   = (const float*)d_in[14];
    float* out = (float*)d_out;

    int V = in_sizes[0] / 3;
    long fixed = 69L + 69L + 1L + 3L + 3L * (long)V;
    int B = (int)(((long)out_size - fixed) / (3L * (long)V));

    static int smem_set = 0;
    if (!smem_set) {
        cudaFuncSetAttribute(lbs_kernel,
                             cudaFuncAttributeMaxDynamicSharedMemorySize, SMEM_BYTES);
        smem_set = 1;
    }

    prep_kernel<<<1, 32>>>(jr, p0, p1, p2, p3, p4, p5, p12, p13,
                           disp, scale, loc, out, B, V);

    int blocks = (V + VPB - 1) / VPB;
    lbs_kernel<<<blocks, TPB, SMEM_BYTES>>>(vt, sk, la, out, V, B);
}

// round 7
// speedup vs baseline: 1.1651x; 1.1651x over previous
#include <cuda_runtime.h>
#include <math.h>

#define J   23
#define TPB 256
#define VPB 256
#define PI_F 3.14159265358979323846f

__constant__ int cPAR[J] = {-1,0,1,1,3,4,5,4,7,4,9,1,11,12,13,12,15,12,17,0,19,0,21};

// packed A (69 float4 = 276 floats) + constants (c, ox, oy, oz) at [276..279]
static __device__ __align__(16) float g_pack[280];
__constant__ __align__(16) float c_pack[280];

// ---------------- Prep: one warp. pose -> Rodrigues -> FK -> A + small outputs ----------------
__global__ void __launch_bounds__(32) prep_kernel(
    const float* __restrict__ jr,
    const float* __restrict__ p0, const float* __restrict__ p1,
    const float* __restrict__ p2, const float* __restrict__ p3,
    const float* __restrict__ p4, const float* __restrict__ p5,
    const float* __restrict__ p12, const float* __restrict__ p13,
    const float* __restrict__ disp, const float* __restrict__ scale,
    const float* __restrict__ loc,
    float* __restrict__ out, int B, int V)
{
    __shared__ float s_Tl[J * 12];
    __shared__ float s_G[J * 12];
    __shared__ float s_pose[J * 3];

    const int tid = threadIdx.x;

    float cst = 0.f, ox = 0.f, oy = 0.f, oz = 0.f;
    if (tid == 31) {
        cst = 0.0035f * scale[0];
        ox = loc[0] + 0.1f * tanhf(disp[0]);
        oy = loc[1] + 0.1f * tanhf(disp[1]);
        oz = loc[2] + 0.1f * tanhf(disp[2]);
        g_pack[276] = cst; g_pack[277] = ox; g_pack[278] = oy; g_pack[279] = oz;
    }

    if (tid < J) {
        float fac = 0.f, sy = 1.f, sz = 1.f;
        const float* pp = p0;
        bool has = true;
        switch (tid) {
            case 0:  fac = PI_F / 2.f; pp = p0;  break;
            case 1:  fac = PI_F / 4.f; pp = p1;  break;
            case 2:  fac = PI_F / 9.f; pp = p2;  break;
            case 3:  fac = PI_F / 3.f; pp = p3;  break;
            case 4:  fac = PI_F / 3.f; pp = p4;  break;
            case 5:  fac = PI_F / 3.f; pp = p5;  break;
            case 11: fac = PI_F / 3.f; pp = p3;  sy = -1.f; sz = -1.f; break;
            case 12: fac = PI_F / 3.f; pp = p12; break;
            case 13: fac = PI_F / 3.f; pp = p13; break;
            default: has = false;
        }
        float px = 0.f, py = 0.f, pz = 0.f;
        if (has) {
            px = fac * tanhf(pp[0]);
            py = sy * fac * tanhf(pp[1]);
            pz = sz * fac * tanhf(pp[2]);
        }
        s_pose[3 * tid + 0] = px;
        s_pose[3 * tid + 1] = py;
        s_pose[3 * tid + 2] = pz;

        float ang = sqrtf(px * px + py * py + pz * pz + 1e-12f);
        float inv = 1.f / ang;
        float x = px * inv, y = py * inv, z = pz * inv;
        float s = sinf(ang), c = cosf(ang), t = 1.f - c;
        float* T = &s_Tl[tid * 12];
        T[0] = 1.f + t * (-(z * z) - (y * y));
        T[1] = -s * z + t * (x * y);
        T[2] =  s * y + t * (x * z);
        T[4] =  s * z + t * (x * y);
        T[5] = 1.f + t * (-(z * z) - (x * x));
        T[6] = -s * x + t * (y * z);
        T[8] = -s * y + t * (x * z);
        T[9] =  s * x + t * (y * z);
        T[10] = 1.f + t * (-(y * y) - (x * x));

        int par = cPAR[tid];
        float jx = jr[3 * tid], jy = jr[3 * tid + 1], jz = jr[3 * tid + 2];
        if (par >= 0) { jx -= jr[3 * par]; jy -= jr[3 * par + 1]; jz -= jr[3 * par + 2]; }
        T[3] = jx; T[7] = jy; T[11] = jz;
    }
    __syncwarp();

    if (tid < 12) s_G[tid] = s_Tl[tid];
    __syncwarp();
    #pragma unroll
    for (int j = 1; j < J; j++) {
        const int p = cPAR[j];
        if (tid < 12) {
            const int r = tid >> 2, c = tid & 3;
            const float* gp = &s_G[p * 12 + r * 4];
            const float* tl = &s_Tl[j * 12];
            float v = gp[0] * tl[0 * 4 + c]
                    + gp[1] * tl[1 * 4 + c]
                    + gp[2] * tl[2 * 4 + c];
            if (c == 3) v += gp[3];
            s_G[j * 12 + tid] = v;
        }
        __syncwarp();
    }

    if (tid < J) {
        const float* g = &s_G[tid * 12];
        float jx = jr[3 * tid], jy = jr[3 * tid + 1], jz = jr[3 * tid + 2];
        float tcx = g[0] * jx + g[1] * jy + g[2] * jz;
        float tcy = g[4] * jx + g[5] * jy + g[6] * jz;
        float tcz = g[8] * jx + g[9] * jy + g[10] * jz;
        float* a = &g_pack[tid * 12];
        a[0] = g[0]; a[1] = g[1]; a[2]  = g[2];  a[3]  = g[3]  - tcx;
        a[4] = g[4]; a[5] = g[5]; a[6]  = g[6];  a[7]  = g[7]  - tcy;
        a[8] = g[8]; a[9] = g[9]; a[10] = g[10]; a[11] = g[11] - tcz;
    }

    const long V3 = 3L * (long)V;
    const long base = (long)B * V3;
    if (tid < J) {
        out[base + 3 * tid + 0] = s_pose[3 * tid + 0];
        out[base + 3 * tid + 1] = s_pose[3 * tid + 1];
        out[base + 3 * tid + 2] = s_pose[3 * tid + 2];
    }
    __syncwarp();
    if (tid == 31) {
        for (int j = 0; j < J; j++) {
            out[base + 69 + 3 * j + 0] = fmaf(cst, s_G[j * 12 + 3],  ox);
            out[base + 69 + 3 * j + 1] = fmaf(cst, s_G[j * 12 + 7],  oy);
            out[base + 69 + 3 * j + 2] = fmaf(cst, s_G[j * 12 + 11], oz);
        }
        out[base + 138] = scale[0];
        out[base + 139] = disp[0];
        out[base + 140] = disp[1];
        out[base + 141] = disp[2];
    }
}

// ---------------- LBS: round-3 structure, A from __constant__ ----------------
__global__ void __launch_bounds__(TPB) lbs_kernel(
    const float* __restrict__ vt,
    const float* __restrict__ sk,
    const float* __restrict__ la,
    float* __restrict__ out, int V, int B)
{
    __shared__ float s_sk[VPB * 23];
    __shared__ float s_vt[VPB * 3];    // reused for results after compute
    __shared__ float s_la[VPB * 3];

    const int tid = threadIdx.x;
    const long v0 = (long)blockIdx.x * VPB;
    const int nv  = (V - (int)v0 < VPB) ? (V - (int)v0) : VPB;
    const long V3 = 3L * (long)V;

    // cooperative vectorized tile loads
    {
        const float4* g4 = (const float4*)(sk + v0 * 23);
        const int nS = (nv * 23) >> 2;
        #pragma unroll 3
        for (int i = tid; i < nS; i += TPB) ((float4*)s_sk)[i] = __ldcs(g4 + i);

        const float4* gv = (const float4*)(vt + v0 * 3);
        const float4* gl = (const float4*)(la + v0 * 3);
        const int n3 = (nv * 3) >> 2;
        for (int i = tid; i < n3; i += TPB) {
            ((float4*)s_vt)[i] = __ldcs(gv + i);
            ((float4*)s_la)[i] = __ldcs(gl + i);
        }
    }
    __syncthreads();

    float rx = 0.f, ry = 0.f, rz = 0.f;
    if (tid < nv) {
        float la0 = s_la[3 * tid + 0], la1 = s_la[3 * tid + 1], la2 = s_la[3 * tid + 2];
        float vx = s_vt[3 * tid + 0] + 0.1f * tanhf(la0);
        float vy = s_vt[3 * tid + 1] + 0.1f * tanhf(la1);
        float vz = s_vt[3 * tid + 2] + 0.1f * tanhf(la2);

        float4 t0 = make_float4(0.f, 0.f, 0.f, 0.f);
        float4 t1 = make_float4(0.f, 0.f, 0.f, 0.f);
        float4 t2 = make_float4(0.f, 0.f, 0.f, 0.f);

        const float4* cA = (const float4*)c_pack;     // 3 float4 per joint, const bank
        const float* skv = &s_sk[tid * 23];
        #pragma unroll
        for (int j = 0; j < J; j++) {
            float w = skv[j];
            float4 a0 = cA[3 * j + 0];
            float4 a1 = cA[3 * j + 1];
            float4 a2 = cA[3 * j + 2];
            t0.x = fmaf(w, a0.x, t0.x); t0.y = fmaf(w, a0.y, t0.y);
            t0.z = fmaf(w, a0.z, t0.z); t0.w = fmaf(w, a0.w, t0.w);
            t1.x = fmaf(w, a1.x, t1.x); t1.y = fmaf(w, a1.y, t1.y);
            t1.z = fmaf(w, a1.z, t1.z); t1.w = fmaf(w, a1.w, t1.w);
            t2.x = fmaf(w, a2.x, t2.x); t2.y = fmaf(w, a2.y, t2.y);
            t2.z = fmaf(w, a2.z, t2.z); t2.w = fmaf(w, a2.w, t2.w);
        }

        float x = fmaf(t0.x, vx, fmaf(t0.y, vy, fmaf(t0.z, vz, t0.w)));
        float y = fmaf(t1.x, vx, fmaf(t1.y, vy, fmaf(t1.z, vz, t1.w)));
        float z = fmaf(t2.x, vx, fmaf(t2.y, vy, fmaf(t2.z, vz, t2.w)));

        float c = c_pack[276];
        rx = fmaf(c, x, c_pack[277]);
        ry = fmaf(c, y, c_pack[278]);
        rz = fmaf(c, z, c_pack[279]);
    }
    __syncthreads();
    if (tid < nv) {
        s_vt[3 * tid + 0] = rx;
        s_vt[3 * tid + 1] = ry;
        s_vt[3 * tid + 2] = rz;
    }
    __syncthreads();

    // cooperative vectorized streaming stores
    {
        const int n3 = (nv * 3) >> 2;
        const float4* r4 = (const float4*)s_vt;
        for (int b = 0; b < B; b++) {
            float4* go = (float4*)(out + (long)b * V3 + v0 * 3);
            for (int i = tid; i < n3; i += TPB) __stcs(go + i, r4[i]);
        }
        const long offLa = (long)B * V3 + 142;
        float2* gl2 = (float2*)(out + offLa + v0 * 3);
        const float2* l2 = (const float2*)s_la;
        const int n2 = (nv * 3) >> 1;
        for (int i = tid; i < n2; i += TPB) __stcs(gl2 + i, l2[i]);
    }
}

extern "C" void kernel_launch(void* const* d_in, const int* in_sizes, int n_in,
                              void* d_out, int out_size)
{
    const float* vt    = (const float*)d_in[0];
    const float* sk    = (const float*)d_in[1];
    const float* jr    = (const float*)d_in[2];
    const float* p0    = (const float*)d_in[3];
    const float* p1    = (const float*)d_in[4];
    const float* p2    = (const float*)d_in[5];
    const float* p3    = (const float*)d_in[6];
    const float* p4    = (const float*)d_in[7];
    const float* p5    = (const float*)d_in[8];
    const float* p12   = (const float*)d_in[9];
    const float* p13   = (const float*)d_in[10];
    const float* la    = (const float*)d_in[11];
    const float* disp  = (const float*)d_in[12];
    const float* scale = (const float*)d_in[13];
    const float* loc   = (const float*)d_in[14];
    float* out = (float*)d_out;

    int V = in_sizes[0] / 3;
    long fixed = 69L + 69L + 1L + 3L + 3L * (long)V;
    int B = (int)(((long)out_size - fixed) / (3L * (long)V));

    prep_kernel<<<1, 32>>>(jr, p0, p1, p2, p3, p4, p5, p12, p13,
                           disp, scale, loc, out, B, V);

    // copy A + constants into the constant bank (captured D2D copy)
    static void* g_pack_addr = nullptr;
    if (!g_pack_addr) cudaGetSymbolAddress(&g_pack_addr, g_pack);
    cudaMemcpyToSymbolAsync(c_pack, g_pack_addr, 280 * sizeof(float), 0,
                            cudaMemcpyDeviceToDevice, 0);

    int blocks = (V + VPB - 1) / VPB;
    lbs_kernel<<<blocks, TPB>>>(vt, sk, la, out, V, B);
}

// round 8
// speedup vs baseline: 1.2699x; 1.0900x over previous
#include <cuda_runtime.h>
#include <math.h>

#define J   23
#define TPB 256
#define VPB 256
#define PI_F 3.14159265358979323846f

__constant__ int cPAR[J] = {-1,0,1,1,3,4,5,4,7,4,9,1,11,12,13,12,15,12,17,0,19,0,21};

// packed A (69 float4 = 276 floats) + constants (c, ox, oy, oz) at [276..279]
static __device__ __align__(16) float g_pack[280];
__constant__ __align__(16) float c_pack[280];

typedef unsigned long long u64;

__device__ __forceinline__ void fma2(u64& d, u64 a, u64 b) {
    asm("fma.rn.f32x2 %0, %1, %2, %0;" : "+l"(d) : "l"(a), "l"(b));
}
__device__ __forceinline__ u64 pack2(float v) {
    u64 r;
    asm("mov.b64 %0, {%1, %1};" : "=l"(r) : "f"(v));
    return r;
}
__device__ __forceinline__ void unpack2(u64 v, float& lo, float& hi) {
    asm("mov.b64 {%0, %1}, %2;" : "=f"(lo), "=f"(hi) : "l"(v));
}
__device__ __forceinline__ float tanha(float x) {
    float y;
    asm("tanh.approx.f32 %0, %1;" : "=f"(y) : "f"(x));
    return y;
}

// ---------------- Prep: one warp. pose -> Rodrigues -> FK -> A + small outputs ----------------
__global__ void __launch_bounds__(32) prep_kernel(
    const float* __restrict__ jr,
    const float* __restrict__ p0, const float* __restrict__ p1,
    const float* __restrict__ p2, const float* __restrict__ p3,
    const float* __restrict__ p4, const float* __restrict__ p5,
    const float* __restrict__ p12, const float* __restrict__ p13,
    const float* __restrict__ disp, const float* __restrict__ scale,
    const float* __restrict__ loc,
    float* __restrict__ out, int B, int V)
{
    __shared__ float s_Tl[J * 12];
    __shared__ float s_G[J * 12];
    __shared__ float s_pose[J * 3];

    const int tid = threadIdx.x;

    float cst = 0.f, ox = 0.f, oy = 0.f, oz = 0.f;
    if (tid == 31) {
        cst = 0.0035f * scale[0];
        ox = loc[0] + 0.1f * tanhf(disp[0]);
        oy = loc[1] + 0.1f * tanhf(disp[1]);
        oz = loc[2] + 0.1f * tanhf(disp[2]);
        g_pack[276] = cst; g_pack[277] = ox; g_pack[278] = oy; g_pack[279] = oz;
    }

    if (tid < J) {
        float fac = 0.f, sy = 1.f, sz = 1.f;
        const float* pp = p0;
        bool has = true;
        switch (tid) {
            case 0:  fac = PI_F / 2.f; pp = p0;  break;
            case 1:  fac = PI_F / 4.f; pp = p1;  break;
            case 2:  fac = PI_F / 9.f; pp = p2;  break;
            case 3:  fac = PI_F / 3.f; pp = p3;  break;
            case 4:  fac = PI_F / 3.f; pp = p4;  break;
            case 5:  fac = PI_F / 3.f; pp = p5;  break;
            case 11: fac = PI_F / 3.f; pp = p3;  sy = -1.f; sz = -1.f; break;
            case 12: fac = PI_F / 3.f; pp = p12; break;
            case 13: fac = PI_F / 3.f; pp = p13; break;
            default: has = false;
        }
        float px = 0.f, py = 0.f, pz = 0.f;
        if (has) {
            px = fac * tanhf(pp[0]);
            py = sy * fac * tanhf(pp[1]);
            pz = sz * fac * tanhf(pp[2]);
        }
        s_pose[3 * tid + 0] = px;
        s_pose[3 * tid + 1] = py;
        s_pose[3 * tid + 2] = pz;

        float ang = sqrtf(px * px + py * py + pz * pz + 1e-12f);
        float inv = 1.f / ang;
        float x = px * inv, y = py * inv, z = pz * inv;
        float s = sinf(ang), c = cosf(ang), t = 1.f - c;
        float* T = &s_Tl[tid * 12];
        T[0] = 1.f + t * (-(z * z) - (y * y));
        T[1] = -s * z + t * (x * y);
        T[2] =  s * y + t * (x * z);
        T[4] =  s * z + t * (x * y);
        T[5] = 1.f + t * (-(z * z) - (x * x));
        T[6] = -s * x + t * (y * z);
        T[8] = -s * y + t * (x * z);
        T[9] =  s * x + t * (y * z);
        T[10] = 1.f + t * (-(y * y) - (x * x));

        int par = cPAR[tid];
        float jx = jr[3 * tid], jy = jr[3 * tid + 1], jz = jr[3 * tid + 2];
        if (par >= 0) { jx -= jr[3 * par]; jy -= jr[3 * par + 1]; jz -= jr[3 * par + 2]; }
        T[3] = jx; T[7] = jy; T[11] = jz;
    }
    __syncwarp();

    if (tid < 12) s_G[tid] = s_Tl[tid];
    __syncwarp();
    #pragma unroll
    for (int j = 1; j < J; j++) {
        const int p = cPAR[j];
        if (tid < 12) {
            const int r = tid >> 2, c = tid & 3;
            const float* gp = &s_G[p * 12 + r * 4];
            const float* tl = &s_Tl[j * 12];
            float v = gp[0] * tl[0 * 4 + c]
                    + gp[1] * tl[1 * 4 + c]
                    + gp[2] * tl[2 * 4 + c];
            if (c == 3) v += gp[3];
            s_G[j * 12 + tid] = v;
        }
        __syncwarp();
    }

    if (tid < J) {
        const float* g = &s_G[tid * 12];
        float jx = jr[3 * tid], jy = jr[3 * tid + 1], jz = jr[3 * tid + 2];
        float tcx = g[0] * jx + g[1] * jy + g[2] * jz;
        float tcy = g[4] * jx + g[5] * jy + g[6] * jz;
        float tcz = g[8] * jx + g[9] * jy + g[10] * jz;
        float* a = &g_pack[tid * 12];
        a[0] = g[0]; a[1] = g[1]; a[2]  = g[2];  a[3]  = g[3]  - tcx;
        a[4] = g[4]; a[5] = g[5]; a[6]  = g[6];  a[7]  = g[7]  - tcy;
        a[8] = g[8]; a[9] = g[9]; a[10] = g[10]; a[11] = g[11] - tcz;
    }

    const long V3 = 3L * (long)V;
    const long base = (long)B * V3;
    if (tid < J) {
        out[base + 3 * tid + 0] = s_pose[3 * tid + 0];
        out[base + 3 * tid + 1] = s_pose[3 * tid + 1];
        out[base + 3 * tid + 2] = s_pose[3 * tid + 2];
    }
    __syncwarp();
    if (tid == 31) {
        for (int j = 0; j < J; j++) {
            out[base + 69 + 3 * j + 0] = fmaf(cst, s_G[j * 12 + 3],  ox);
            out[base + 69 + 3 * j + 1] = fmaf(cst, s_G[j * 12 + 7],  oy);
            out[base + 69 + 3 * j + 2] = fmaf(cst, s_G[j * 12 + 11], oz);
        }
        out[base + 138] = scale[0];
        out[base + 139] = disp[0];
        out[base + 140] = disp[1];
        out[base + 141] = disp[2];
    }
}

// ---------------- LBS: constant-bank A, f32x2 accumulation, approx tanh ----------------
__global__ void __launch_bounds__(TPB) lbs_kernel(
    const float* __restrict__ vt,
    const float* __restrict__ sk,
    const float* __restrict__ la,
    float* __restrict__ out, int V, int B)
{
    __shared__ float s_sk[VPB * 23];
    __shared__ float s_vt[VPB * 3];    // reused for results after compute
    __shared__ float s_la[VPB * 3];

    const int tid = threadIdx.x;
    const long v0 = (long)blockIdx.x * VPB;
    const int nv  = (V - (int)v0 < VPB) ? (V - (int)v0) : VPB;
    const long V3 = 3L * (long)V;

    // cooperative vectorized tile loads (int tile-local indices)
    {
        const float4* g4 = (const float4*)(sk + v0 * 23);
        float4* d4 = (float4*)s_sk;
        const int nS = (nv * 23) >> 2;
        #pragma unroll 3
        for (int i = tid; i < nS; i += TPB) d4[i] = __ldcs(g4 + i);

        const float4* gv = (const float4*)(vt + v0 * 3);
        const float4* gl = (const float4*)(la + v0 * 3);
        float4* dv = (float4*)s_vt;
        float4* dl = (float4*)s_la;
        const int n3 = (nv * 3) >> 2;
        for (int i = tid; i < n3; i += TPB) {
            dv[i] = __ldcs(gv + i);
            dl[i] = __ldcs(gl + i);
        }
    }
    __syncthreads();

    float rx = 0.f, ry = 0.f, rz = 0.f;
    if (tid < nv) {
        float la0 = s_la[3 * tid + 0], la1 = s_la[3 * tid + 1], la2 = s_la[3 * tid + 2];
        float vx = s_vt[3 * tid + 0] + 0.1f * tanha(la0);
        float vy = s_vt[3 * tid + 1] + 0.1f * tanha(la1);
        float vz = s_vt[3 * tid + 2] + 0.1f * tanha(la2);

        // T = sum_j w_j A_j with packed f32x2 (6 accumulators)
        u64 acc0 = 0, acc1 = 0, acc2 = 0, acc3 = 0, acc4 = 0, acc5 = 0;
        const u64* cA2 = (const u64*)c_pack;   // 6 u64 per joint
        const float* skv = &s_sk[tid * 23];
        #pragma unroll
        for (int j = 0; j < J; j++) {
            const u64 w2 = pack2(skv[j]);
            fma2(acc0, w2, cA2[6 * j + 0]);
            fma2(acc1, w2, cA2[6 * j + 1]);
            fma2(acc2, w2, cA2[6 * j + 2]);
            fma2(acc3, w2, cA2[6 * j + 3]);
            fma2(acc4, w2, cA2[6 * j + 4]);
            fma2(acc5, w2, cA2[6 * j + 5]);
        }

        float t0x, t0y, t0z, t0w, t1x, t1y, t1z, t1w, t2x, t2y, t2z, t2w;
        unpack2(acc0, t0x, t0y); unpack2(acc1, t0z, t0w);
        unpack2(acc2, t1x, t1y); unpack2(acc3, t1z, t1w);
        unpack2(acc4, t2x, t2y); unpack2(acc5, t2z, t2w);

        float x = fmaf(t0x, vx, fmaf(t0y, vy, fmaf(t0z, vz, t0w)));
        float y = fmaf(t1x, vx, fmaf(t1y, vy, fmaf(t1z, vz, t1w)));
        float z = fmaf(t2x, vx, fmaf(t2y, vy, fmaf(t2z, vz, t2w)));

        float c = c_pack[276];
        rx = fmaf(c, x, c_pack[277]);
        ry = fmaf(c, y, c_pack[278]);
        rz = fmaf(c, z, c_pack[279]);
    }
    __syncthreads();
    if (tid < nv) {
        s_vt[3 * tid + 0] = rx;
        s_vt[3 * tid + 1] = ry;
        s_vt[3 * tid + 2] = rz;
    }
    __syncthreads();

    // cooperative vectorized streaming stores (hoisted pointers, int inner loops)
    {
        const int n3 = (nv * 3) >> 2;
        const float4* r4 = (const float4*)s_vt;
        float4* go = (float4*)(out + v0 * 3);
        const long stride4 = V3 >> 2;          // V3 divisible by 4 (V = 1e6)
        for (int b = 0; b < B; b++) {
            for (int i = tid; i < n3; i += TPB) __stcs(go + i, r4[i]);
            go += stride4;
        }
        const long offLa = (long)B * V3 + 142;
        float2* gl2 = (float2*)(out + offLa + v0 * 3);
        const float2* l2 = (const float2*)s_la;
        const int n2 = (nv * 3) >> 1;
        for (int i = tid; i < n2; i += TPB) __stcs(gl2 + i, l2[i]);
    }
}

extern "C" void kernel_launch(void* const* d_in, const int* in_sizes, int n_in,
                              void* d_out, int out_size)
{
    const float* vt    = (const float*)d_in[0];
    const float* sk    = (const float*)d_in[1];
    const float* jr    = (const float*)d_in[2];
    const float* p0    = (const float*)d_in[3];
    const float* p1    = (const float*)d_in[4];
    const float* p2    = (const float*)d_in[5];
    const float* p3    = (const float*)d_in[6];
    const float* p4    = (const float*)d_in[7];
    const float* p5    = (const float*)d_in[8];
    const float* p12   = (const float*)d_in[9];
    const float* p13   = (const float*)d_in[10];
    const float* la    = (const float*)d_in[11];
    const float* disp  = (const float*)d_in[12];
    const float* scale = (const float*)d_in[13];
    const float* loc   = (const float*)d_in[14];
    float* out = (float*)d_out;

    int V = in_sizes[0] / 3;
    long fixed = 69L + 69L + 1L + 3L + 3L * (long)V;
    int B = (int)(((long)out_size - fixed) / (3L * (long)V));

    prep_kernel<<<1, 32>>>(jr, p0, p1, p2, p3, p4, p5, p12, p13,
                           disp, scale, loc, out, B, V);

    static void* g_pack_addr = nullptr;
    if (!g_pack_addr) cudaGetSymbolAddress(&g_pack_addr, g_pack);
    cudaMemcpyToSymbolAsync(c_pack, g_pack_addr, 280 * sizeof(float), 0,
                            cudaMemcpyDeviceToDevice, 0);

    int blocks = (V + VPB - 1) / VPB;
    lbs_kernel<<<blocks, TPB>>>(vt, sk, la, out, V, B);
}

// round 9
// speedup vs baseline: 1.4573x; 1.1476x over previous
#include <cuda_runtime.h>
#include <math.h>

#define J   23
#define TPB 256
#define VPB 256
#define PI_F 3.14159265358979323846f

__constant__ int cPAR[J] = {-1,0,1,1,3,4,5,4,7,4,9,1,11,12,13,12,15,12,17,0,19,0,21};

// packed A (69 float4 = 276 floats) + constants (c, ox, oy, oz) at [276..279]
__constant__ __align__(16) float c_pack[280];

typedef unsigned long long u64;

__device__ __forceinline__ void fma2(u64& d, u64 a, u64 b) {
    asm("fma.rn.f32x2 %0, %1, %2, %0;" : "+l"(d) : "l"(a), "l"(b));
}
__device__ __forceinline__ u64 pack2(float v) {
    u64 r;
    asm("mov.b64 %0, {%1, %1};" : "=l"(r) : "f"(v));
    return r;
}
__device__ __forceinline__ void unpack2(u64 v, float& lo, float& hi) {
    asm("mov.b64 {%0, %1}, %2;" : "=f"(lo), "=f"(hi) : "l"(v));
}
__device__ __forceinline__ float tanha(float x) {
    float y;
    asm("tanh.approx.f32 %0, %1;" : "=f"(y) : "f"(x));
    return y;
}

// ---------------- Prep: one warp. Writes A + consts straight into the constant bank ----------------
__global__ void __launch_bounds__(32) prep_kernel(
    float* __restrict__ cpack,          // device address of c_pack
    const float* __restrict__ jr,
    const float* __restrict__ p0, const float* __restrict__ p1,
    const float* __restrict__ p2, const float* __restrict__ p3,
    const float* __restrict__ p4, const float* __restrict__ p5,
    const float* __restrict__ p12, const float* __restrict__ p13,
    const float* __restrict__ disp, const float* __restrict__ scale,
    const float* __restrict__ loc,
    float* __restrict__ out, int B, int V)
{
    __shared__ float s_Tl[J * 12];
    __shared__ float s_G[J * 12];
    __shared__ float s_pose[J * 3];

    const int tid = threadIdx.x;

    float cst = 0.f, ox = 0.f, oy = 0.f, oz = 0.f;
    if (tid == 31) {
        cst = 0.0035f * scale[0];
        ox = loc[0] + 0.1f * tanhf(disp[0]);
        oy = loc[1] + 0.1f * tanhf(disp[1]);
        oz = loc[2] + 0.1f * tanhf(disp[2]);
        cpack[276] = cst; cpack[277] = ox; cpack[278] = oy; cpack[279] = oz;
    }

    if (tid < J) {
        float fac = 0.f, sy = 1.f, sz = 1.f;
        const float* pp = p0;
        bool has = true;
        switch (tid) {
            case 0:  fac = PI_F / 2.f; pp = p0;  break;
            case 1:  fac = PI_F / 4.f; pp = p1;  break;
            case 2:  fac = PI_F / 9.f; pp = p2;  break;
            case 3:  fac = PI_F / 3.f; pp = p3;  break;
            case 4:  fac = PI_F / 3.f; pp = p4;  break;
            case 5:  fac = PI_F / 3.f; pp = p5;  break;
            case 11: fac = PI_F / 3.f; pp = p3;  sy = -1.f; sz = -1.f; break;
            case 12: fac = PI_F / 3.f; pp = p12; break;
            case 13: fac = PI_F / 3.f; pp = p13; break;
            default: has = false;
        }
        float px = 0.f, py = 0.f, pz = 0.f;
        if (has) {
            px = fac * tanhf(pp[0]);
            py = sy * fac * tanhf(pp[1]);
            pz = sz * fac * tanhf(pp[2]);
        }
        s_pose[3 * tid + 0] = px;
        s_pose[3 * tid + 1] = py;
        s_pose[3 * tid + 2] = pz;

        float ang = sqrtf(px * px + py * py + pz * pz + 1e-12f);
        float inv = 1.f / ang;
        float x = px * inv, y = py * inv, z = pz * inv;
        float s = __sinf(ang), c = __cosf(ang), t = 1.f - c;
        float* T = &s_Tl[tid * 12];
        T[0] = 1.f + t * (-(z * z) - (y * y));
        T[1] = -s * z + t * (x * y);
        T[2] =  s * y + t * (x * z);
        T[4] =  s * z + t * (x * y);
        T[5] = 1.f + t * (-(z * z) - (x * x));
        T[6] = -s * x + t * (y * z);
        T[8] = -s * y + t * (x * z);
        T[9] =  s * x + t * (y * z);
        T[10] = 1.f + t * (-(y * y) - (x * x));

        int par = cPAR[tid];
        float jx = jr[3 * tid], jy = jr[3 * tid + 1], jz = jr[3 * tid + 2];
        if (par >= 0) { jx -= jr[3 * par]; jy -= jr[3 * par + 1]; jz -= jr[3 * par + 2]; }
        T[3] = jx; T[7] = jy; T[11] = jz;
    }
    __syncwarp();

    if (tid < 12) s_G[tid] = s_Tl[tid];
    __syncwarp();
    #pragma unroll
    for (int j = 1; j < J; j++) {
        const int p = cPAR[j];
        if (tid < 12) {
            const int r = tid >> 2, c = tid & 3;
            const float* gp = &s_G[p * 12 + r * 4];
            const float* tl = &s_Tl[j * 12];
            float v = gp[0] * tl[0 * 4 + c]
                    + gp[1] * tl[1 * 4 + c]
                    + gp[2] * tl[2 * 4 + c];
            if (c == 3) v += gp[3];
            s_G[j * 12 + tid] = v;
        }
        __syncwarp();
    }

    if (tid < J) {
        const float* g = &s_G[tid * 12];
        float jx = jr[3 * tid], jy = jr[3 * tid + 1], jz = jr[3 * tid + 2];
        float tcx = g[0] * jx + g[1] * jy + g[2] * jz;
        float tcy = g[4] * jx + g[5] * jy + g[6] * jz;
        float tcz = g[8] * jx + g[9] * jy + g[10] * jz;
        float* a = &cpack[tid * 12];
        a[0] = g[0]; a[1] = g[1]; a[2]  = g[2];  a[3]  = g[3]  - tcx;
        a[4] = g[4]; a[5] = g[5]; a[6]  = g[6];  a[7]  = g[7]  - tcy;
        a[8] = g[8]; a[9] = g[9]; a[10] = g[10]; a[11] = g[11] - tcz;
    }

    const long V3 = 3L * (long)V;
    const long base = (long)B * V3;
    if (tid < J) {
        out[base + 3 * tid + 0] = s_pose[3 * tid + 0];
        out[base + 3 * tid + 1] = s_pose[3 * tid + 1];
        out[base + 3 * tid + 2] = s_pose[3 * tid + 2];
    }
    __syncwarp();
    if (tid == 31) {
        for (int j = 0; j < J; j++) {
            out[base + 69 + 3 * j + 0] = fmaf(cst, s_G[j * 12 + 3],  ox);
            out[base + 69 + 3 * j + 1] = fmaf(cst, s_G[j * 12 + 7],  oy);
            out[base + 69 + 3 * j + 2] = fmaf(cst, s_G[j * 12 + 11], oz);
        }
        out[base + 138] = scale[0];
        out[base + 139] = disp[0];
        out[base + 140] = disp[1];
        out[base + 141] = disp[2];
    }
}

// ---------------- LBS: constant-bank A, f32x2 accumulation, full-tile fast paths ----------------
__global__ void __launch_bounds__(TPB) lbs_kernel(
    const float* __restrict__ vt,
    const float* __restrict__ sk,
    const float* __restrict__ la,
    float* __restrict__ out, int V, int B)
{
    __shared__ float s_sk[VPB * 23];
    __shared__ float s_vt[VPB * 3];    // reused for results after compute
    __shared__ float s_la[VPB * 3];

    const int tid = threadIdx.x;
    const long v0 = (long)blockIdx.x * VPB;
    const int nv  = (V - (int)v0 < VPB) ? (V - (int)v0) : VPB;
    const long V3 = 3L * (long)V;
    const bool full = (nv == VPB);

    // cooperative vectorized tile loads
    {
        const float4* g4 = (const float4*)(sk + v0 * 23);
        float4* d4 = (float4*)s_sk;
        const float4* gv = (const float4*)(vt + v0 * 3);
        const float4* gl = (const float4*)(la + v0 * 3);
        float4* dv = (float4*)s_vt;
        float4* dl = (float4*)s_la;
        if (full) {
            // VPB*23/4 = 1472 float4 -> 5 full strides + partial (192)
            #pragma unroll
            for (int k = 0; k < 5; k++) {
                const int i = tid + k * TPB;
                d4[i] = __ldcs(g4 + i);
            }
            {
                const int i = tid + 5 * TPB;
                if (i < 1472) d4[i] = __ldcs(g4 + i);
            }
            // VPB*3/4 = 192 float4
            if (tid < 192) {
                dv[tid] = __ldcs(gv + tid);
                dl[tid] = __ldcs(gl + tid);
            }
        } else {
            const int nS = (nv * 23) >> 2;
            for (int i = tid; i < nS; i += TPB) d4[i] = __ldcs(g4 + i);
            const int n3 = (nv * 3) >> 2;
            for (int i = tid; i < n3; i += TPB) {
                dv[i] = __ldcs(gv + i);
                dl[i] = __ldcs(gl + i);
            }
        }
    }
    __syncthreads();

    float rx = 0.f, ry = 0.f, rz = 0.f;
    if (tid < nv) {
        float la0 = s_la[3 * tid + 0], la1 = s_la[3 * tid + 1], la2 = s_la[3 * tid + 2];
        float vx = s_vt[3 * tid + 0] + 0.1f * tanha(la0);
        float vy = s_vt[3 * tid + 1] + 0.1f * tanha(la1);
        float vz = s_vt[3 * tid + 2] + 0.1f * tanha(la2);

        // T = sum_j w_j A_j with packed f32x2 (6 accumulators)
        u64 acc0 = 0, acc1 = 0, acc2 = 0, acc3 = 0, acc4 = 0, acc5 = 0;
        const u64* cA2 = (const u64*)c_pack;   // 6 u64 per joint
        const float* skv = &s_sk[tid * 23];
        #pragma unroll
        for (int j = 0; j < J; j++) {
            const u64 w2 = pack2(skv[j]);
            fma2(acc0, w2, cA2[6 * j + 0]);
            fma2(acc1, w2, cA2[6 * j + 1]);
            fma2(acc2, w2, cA2[6 * j + 2]);
            fma2(acc3, w2, cA2[6 * j + 3]);
            fma2(acc4, w2, cA2[6 * j + 4]);
            fma2(acc5, w2, cA2[6 * j + 5]);
        }

        float t0x, t0y, t0z, t0w, t1x, t1y, t1z, t1w, t2x, t2y, t2z, t2w;
        unpack2(acc0, t0x, t0y); unpack2(acc1, t0z, t0w);
        unpack2(acc2, t1x, t1y); unpack2(acc3, t1z, t1w);
        unpack2(acc4, t2x, t2y); unpack2(acc5, t2z, t2w);

        float x = fmaf(t0x, vx, fmaf(t0y, vy, fmaf(t0z, vz, t0w)));
        float y = fmaf(t1x, vx, fmaf(t1y, vy, fmaf(t1z, vz, t1w)));
        float z = fmaf(t2x, vx, fmaf(t2y, vy, fmaf(t2z, vz, t2w)));

        float c = c_pack[276];
        rx = fmaf(c, x, c_pack[277]);
        ry = fmaf(c, y, c_pack[278]);
        rz = fmaf(c, z, c_pack[279]);
    }
    __syncthreads();
    if (tid < nv) {
        s_vt[3 * tid + 0] = rx;
        s_vt[3 * tid + 1] = ry;
        s_vt[3 * tid + 2] = rz;
    }
    __syncthreads();

    // cooperative vectorized streaming stores
    {
        const float4* r4 = (const float4*)s_vt;
        const float2* l2 = (const float2*)s_la;
        const long offLa = (long)B * V3 + 142;
        if (full) {
            if (tid < 192) {
                const float4 val = r4[tid];
                float4* go = (float4*)(out + v0 * 3);
                const long stride4 = V3 >> 2;
                for (int b = 0; b < B; b++) {
                    __stcs(go + tid, val);
                    go += stride4;
                }
            }
            // la passthrough: 384 float2
            float2* gl2 = (float2*)(out + offLa + v0 * 3);
            __stcs(gl2 + tid, l2[tid]);
            if (tid < 128) __stcs(gl2 + tid + 256, l2[tid + 256]);
        } else {
            const int n3 = (nv * 3) >> 2;
            float4* go = (float4*)(out + v0 * 3);
            const long stride4 = V3 >> 2;
            for (int b = 0; b < B; b++) {
                for (int i = tid; i < n3; i += TPB) __stcs(go + i, r4[i]);
                go += stride4;
            }
            float2* gl2 = (float2*)(out + offLa + v0 * 3);
            const int n2 = (nv * 3) >> 1;
            for (int i = tid; i < n2; i += TPB) __stcs(gl2 + i, l2[i]);
        }
    }
}

extern "C" void kernel_launch(void* const* d_in, const int* in_sizes, int n_in,
                              void* d_out, int out_size)
{
    const float* vt    = (const float*)d_in[0];
    const float* sk    = (const float*)d_in[1];
    const float* jr    = (const float*)d_in[2];
    const float* p0    = (const float*)d_in[3];
    const float* p1    = (const float*)d_in[4];
    const float* p2    = (const float*)d_in[5];
    const float* p3    = (const float*)d_in[6];
    const float* p4    = (const float*)d_in[7];
    const float* p5    = (const float*)d_in[8];
    const float* p12   = (const float*)d_in[9];
    const float* p13   = (const float*)d_in[10];
    const float* la    = (const float*)d_in[11];
    const float* disp  = (const float*)d_in[12];
    const float* scale = (const float*)d_in[13];
    const float* loc   = (const float*)d_in[14];
    float* out = (float*)d_out;

    int V = in_sizes[0] / 3;
    long fixed = 69L + 69L + 1L + 3L + 3L * (long)V;
    int B = (int)(((long)out_size - fixed) / (3L * (long)V));

    // device address of the constant bank backing store (no allocation)
    static float* cpack_dev = nullptr;
    if (!cpack_dev) {
        void* p = nullptr;
        cudaGetSymbolAddress(&p, c_pack);
        cpack_dev = (float*)p;
    }

    prep_kernel<<<1, 32>>>(cpack_dev, jr, p0, p1, p2, p3, p4, p5, p12, p13,
                           disp, scale, loc, out, B, V);

    int blocks = (V + VPB - 1) / VPB;
    lbs_kernel<<<blocks, TPB>>>(vt, sk, la, out, V, B);
}

// round 10
// speedup vs baseline: 1.7259x; 1.1843x over previous
#include <cuda_runtime.h>
#include <math.h>

#define J   23
#define TPB 256
#define VPB 256
#define PI_F 3.14159265358979323846f

__constant__ int cPAR[J] = {-1,0,1,1,3,4,5,4,7,4,9,1,11,12,13,12,15,12,17,0,19,0,21};

// packed A (69 float4 = 276 floats) + constants (c, ox, oy, oz) at [276..279]
__constant__ __align__(16) float c_pack[280];

typedef unsigned long long u64;

__device__ __forceinline__ void fma2(u64& d, u64 a, u64 b) {
    asm("fma.rn.f32x2 %0, %1, %2, %0;" : "+l"(d) : "l"(a), "l"(b));
}
__device__ __forceinline__ u64 pack2(float v) {
    u64 r;
    asm("mov.b64 %0, {%1, %1};" : "=l"(r) : "f"(v));
    return r;
}
__device__ __forceinline__ void unpack2(u64 v, float& lo, float& hi) {
    asm("mov.b64 {%0, %1}, %2;" : "=f"(lo), "=f"(hi) : "l"(v));
}
__device__ __forceinline__ float tanha(float x) {
    float y;
    asm("tanh.approx.f32 %0, %1;" : "=f"(y) : "f"(x));
    return y;
}

// ---------------- Prep: one warp; writes A + consts into the constant bank, triggers PDL ----------------
__global__ void __launch_bounds__(32) prep_kernel(
    float* __restrict__ cpack,
    const float* __restrict__ jr,
    const float* __restrict__ p0, const float* __restrict__ p1,
    const float* __restrict__ p2, const float* __restrict__ p3,
    const float* __restrict__ p4, const float* __restrict__ p5,
    const float* __restrict__ p12, const float* __restrict__ p13,
    const float* __restrict__ disp, const float* __restrict__ scale,
    const float* __restrict__ loc,
    float* __restrict__ out, int B, int V)
{
    __shared__ float s_Tl[J * 12];
    __shared__ float s_G[J * 12];
    __shared__ float s_pose[J * 3];

    const int tid = threadIdx.x;

    float cst = 0.f, ox = 0.f, oy = 0.f, oz = 0.f;
    if (tid == 31) {
        cst = 0.0035f * scale[0];
        ox = loc[0] + 0.1f * tanhf(disp[0]);
        oy = loc[1] + 0.1f * tanhf(disp[1]);
        oz = loc[2] + 0.1f * tanhf(disp[2]);
        cpack[276] = cst; cpack[277] = ox; cpack[278] = oy; cpack[279] = oz;
    }

    if (tid < J) {
        float fac = 0.f, sy = 1.f, sz = 1.f;
        const float* pp = p0;
        bool has = true;
        switch (tid) {
            case 0:  fac = PI_F / 2.f; pp = p0;  break;
            case 1:  fac = PI_F / 4.f; pp = p1;  break;
            case 2:  fac = PI_F / 9.f; pp = p2;  break;
            case 3:  fac = PI_F / 3.f; pp = p3;  break;
            case 4:  fac = PI_F / 3.f; pp = p4;  break;
            case 5:  fac = PI_F / 3.f; pp = p5;  break;
            case 11: fac = PI_F / 3.f; pp = p3;  sy = -1.f; sz = -1.f; break;
            case 12: fac = PI_F / 3.f; pp = p12; break;
            case 13: fac = PI_F / 3.f; pp = p13; break;
            default: has = false;
        }
        float px = 0.f, py = 0.f, pz = 0.f;
        if (has) {
            px = fac * tanhf(pp[0]);
            py = sy * fac * tanhf(pp[1]);
            pz = sz * fac * tanhf(pp[2]);
        }
        s_pose[3 * tid + 0] = px;
        s_pose[3 * tid + 1] = py;
        s_pose[3 * tid + 2] = pz;

        float ang = sqrtf(px * px + py * py + pz * pz + 1e-12f);
        float inv = 1.f / ang;
        float x = px * inv, y = py * inv, z = pz * inv;
        float s = __sinf(ang), c = __cosf(ang), t = 1.f - c;
        float* T = &s_Tl[tid * 12];
        T[0] = 1.f + t * (-(z * z) - (y * y));
        T[1] = -s * z + t * (x * y);
        T[2] =  s * y + t * (x * z);
        T[4] =  s * z + t * (x * y);
        T[5] = 1.f + t * (-(z * z) - (x * x));
        T[6] = -s * x + t * (y * z);
        T[8] = -s * y + t * (x * z);
        T[9] =  s * x + t * (y * z);
        T[10] = 1.f + t * (-(y * y) - (x * x));

        int par = cPAR[tid];
        float jx = jr[3 * tid], jy = jr[3 * tid + 1], jz = jr[3 * tid + 2];
        if (par >= 0) { jx -= jr[3 * par]; jy -= jr[3 * par + 1]; jz -= jr[3 * par + 2]; }
        T[3] = jx; T[7] = jy; T[11] = jz;
    }
    __syncwarp();

    if (tid < 12) s_G[tid] = s_Tl[tid];
    __syncwarp();
    #pragma unroll
    for (int j = 1; j < J; j++) {
        const int p = cPAR[j];
        if (tid < 12) {
            const int r = tid >> 2, c = tid & 3;
            const float* gp = &s_G[p * 12 + r * 4];
            const float* tl = &s_Tl[j * 12];
            float v = gp[0] * tl[0 * 4 + c]
                    + gp[1] * tl[1 * 4 + c]
                    + gp[2] * tl[2 * 4 + c];
            if (c == 3) v += gp[3];
            s_G[j * 12 + tid] = v;
        }
        __syncwarp();
    }

    if (tid < J) {
        const float* g = &s_G[tid * 12];
        float jx = jr[3 * tid], jy = jr[3 * tid + 1], jz = jr[3 * tid + 2];
        float tcx = g[0] * jx + g[1] * jy + g[2] * jz;
        float tcy = g[4] * jx + g[5] * jy + g[6] * jz;
        float tcz = g[8] * jx + g[9] * jy + g[10] * jz;
        float* a = &cpack[tid * 12];
        a[0] = g[0]; a[1] = g[1]; a[2]  = g[2];  a[3]  = g[3]  - tcx;
        a[4] = g[4]; a[5] = g[5]; a[6]  = g[6];  a[7]  = g[7]  - tcy;
        a[8] = g[8]; a[9] = g[9]; a[10] = g[10]; a[11] = g[11] - tcz;
    }
    __syncwarp();
    __threadfence();
    cudaTriggerProgrammaticLaunchCompletion();   // lbs may proceed past its grid-dep sync

    // small outputs (independent of lbs)
    const long V3 = 3L * (long)V;
    const long base = (long)B * V3;
    if (tid < J) {
        out[base + 3 * tid + 0] = s_pose[3 * tid + 0];
        out[base + 3 * tid + 1] = s_pose[3 * tid + 1];
        out[base + 3 * tid + 2] = s_pose[3 * tid + 2];
    }
    if (tid == 31) {
        for (int j = 0; j < J; j++) {
            out[base + 69 + 3 * j + 0] = fmaf(cst, s_G[j * 12 + 3],  ox);
            out[base + 69 + 3 * j + 1] = fmaf(cst, s_G[j * 12 + 7],  oy);
            out[base + 69 + 3 * j + 2] = fmaf(cst, s_G[j * 12 + 11], oz);
        }
        out[base + 138] = scale[0];
        out[base + 139] = disp[0];
        out[base + 140] = disp[1];
        out[base + 141] = disp[2];
    }
}

// ---------------- LBS: PDL preamble loads, constant-bank A, f32x2 ----------------
__global__ void __launch_bounds__(TPB, 6) lbs_kernel(
    const float* __restrict__ vt,
    const float* __restrict__ sk,
    const float* __restrict__ la,
    float* __restrict__ out, int V, int B)
{
    __shared__ float s_sk[VPB * 23];
    __shared__ float s_vt[VPB * 3];    // reused for results after compute
    __shared__ float s_la[VPB * 3];

    const int tid = threadIdx.x;
    const long v0 = (long)blockIdx.x * VPB;
    const int nv  = (V - (int)v0 < VPB) ? (V - (int)v0) : VPB;
    const long V3 = 3L * (long)V;
    const bool full = (nv == VPB);
    const long offLa = (long)B * V3 + 142;

    // ---- PDL preamble: tile loads + la passthrough (no dependency on prep) ----
    {
        const float4* g4 = (const float4*)(sk + v0 * 23);
        float4* d4 = (float4*)s_sk;
        const float4* gv = (const float4*)(vt + v0 * 3);
        const float4* gl = (const float4*)(la + v0 * 3);
        float4* dv = (float4*)s_vt;
        float4* dl = (float4*)s_la;
        float2* gl2 = (float2*)(out + offLa + v0 * 3);   // ≡ 2 mod 4 floats → 8B aligned
        if (full) {
            #pragma unroll
            for (int k = 0; k < 5; k++) {
                const int i = tid + k * TPB;
                d4[i] = __ldcs(g4 + i);
            }
            {
                const int i = tid + 5 * TPB;
                if (i < 1472) d4[i] = __ldcs(g4 + i);
            }
            if (tid < 192) {
                dv[tid] = __ldcs(gv + tid);
                float4 lq = __ldcs(gl + tid);
                dl[tid] = lq;
                __stcs(gl2 + 2 * tid + 0, make_float2(lq.x, lq.y));
                __stcs(gl2 + 2 * tid + 1, make_float2(lq.z, lq.w));
            }
        } else {
            const int nS = (nv * 23) >> 2;
            for (int i = tid; i < nS; i += TPB) d4[i] = __ldcs(g4 + i);
            const int n3 = (nv * 3) >> 2;
            for (int i = tid; i < n3; i += TPB) {
                dv[i] = __ldcs(gv + i);
                float4 lq = __ldcs(gl + i);
                dl[i] = lq;
                __stcs(gl2 + 2 * i + 0, make_float2(lq.x, lq.y));
                __stcs(gl2 + 2 * i + 1, make_float2(lq.z, lq.w));
            }
        }
    }

    // wait for prep's c_pack writes, then block-local barrier for smem
    cudaGridDependencySynchronize();
    __syncthreads();

    if (tid < nv) {
        float la0 = s_la[3 * tid + 0], la1 = s_la[3 * tid + 1], la2 = s_la[3 * tid + 2];
        float vx = s_vt[3 * tid + 0] + 0.1f * tanha(la0);
        float vy = s_vt[3 * tid + 1] + 0.1f * tanha(la1);
        float vz = s_vt[3 * tid + 2] + 0.1f * tanha(la2);

        u64 acc0 = 0, acc1 = 0, acc2 = 0, acc3 = 0, acc4 = 0, acc5 = 0;
        const u64* cA2 = (const u64*)c_pack;
        const float* skv = &s_sk[tid * 23];
        #pragma unroll
        for (int j = 0; j < J; j++) {
            const u64 w2 = pack2(skv[j]);
            fma2(acc0, w2, cA2[6 * j + 0]);
            fma2(acc1, w2, cA2[6 * j + 1]);
            fma2(acc2, w2, cA2[6 * j + 2]);
            fma2(acc3, w2, cA2[6 * j + 3]);
            fma2(acc4, w2, cA2[6 * j + 4]);
            fma2(acc5, w2, cA2[6 * j + 5]);
        }

        float t0x, t0y, t0z, t0w, t1x, t1y, t1z, t1w, t2x, t2y, t2z, t2w;
        unpack2(acc0, t0x, t0y); unpack2(acc1, t0z, t0w);
        unpack2(acc2, t1x, t1y); unpack2(acc3, t1z, t1w);
        unpack2(acc4, t2x, t2y); unpack2(acc5, t2z, t2w);

        float x = fmaf(t0x, vx, fmaf(t0y, vy, fmaf(t0z, vz, t0w)));
        float y = fmaf(t1x, vx, fmaf(t1y, vy, fmaf(t1z, vz, t1w)));
        float z = fmaf(t2x, vx, fmaf(t2y, vy, fmaf(t2z, vz, t2w)));

        float c = c_pack[276];
        // each thread overwrites only smem it alone reads -> no barrier needed
        s_vt[3 * tid + 0] = fmaf(c, x, c_pack[277]);
        s_vt[3 * tid + 1] = fmaf(c, y, c_pack[278]);
        s_vt[3 * tid + 2] = fmaf(c, z, c_pack[279]);
    }
    __syncthreads();

    // cooperative vectorized streaming stores (B broadcast copies)
    {
        const float4* r4 = (const float4*)s_vt;
        const long stride4 = V3 >> 2;
        if (full) {
            if (tid < 192) {
                const float4 val = r4[tid];
                float4* go = (float4*)(out + v0 * 3);
                for (int b = 0; b < B; b++) {
                    __stcs(go + tid, val);
                    go += stride4;
                }
            }
        } else {
            const int n3 = (nv * 3) >> 2;
            float4* go = (float4*)(out + v0 * 3);
            for (int b = 0; b < B; b++) {
                for (int i = tid; i < n3; i += TPB) __stcs(go + i, r4[i]);
                go += stride4;
            }
        }
    }
}

extern "C" void kernel_launch(void* const* d_in, const int* in_sizes, int n_in,
                              void* d_out, int out_size)
{
    const float* vt    = (const float*)d_in[0];
    const float* sk    = (const float*)d_in[1];
    const float* jr    = (const float*)d_in[2];
    const float* p0    = (const float*)d_in[3];
    const float* p1    = (const float*)d_in[4];
    const float* p2    = (const float*)d_in[5];
    const float* p3    = (const float*)d_in[6];
    const float* p4    = (const float*)d_in[7];
    const float* p5    = (const float*)d_in[8];
    const float* p12   = (const float*)d_in[9];
    const float* p13   = (const float*)d_in[10];
    const float* la    = (const float*)d_in[11];
    const float* disp  = (const float*)d_in[12];
    const float* scale = (const float*)d_in[13];
    const float* loc   = (const float*)d_in[14];
    float* out = (float*)d_out;

    int V = in_sizes[0] / 3;
    long fixed = 69L + 69L + 1L + 3L + 3L * (long)V;
    int B = (int)(((long)out_size - fixed) / (3L * (long)V));

    static float* cpack_dev = nullptr;
    if (!cpack_dev) {
        void* p = nullptr;
        cudaGetSymbolAddress(&p, c_pack);
        cpack_dev = (float*)p;
    }

    prep_kernel<<<1, 32>>>(cpack_dev, jr, p0, p1, p2, p3, p4, p5, p12, p13,
                           disp, scale, loc, out, B, V);

    int blocks = (V + VPB - 1) / VPB;

    cudaLaunchConfig_t cfg = {};
    cfg.gridDim  = dim3(blocks, 1, 1);
    cfg.blockDim = dim3(TPB, 1, 1);
    cfg.dynamicSmemBytes = 0;
    cfg.stream = 0;
    cudaLaunchAttribute attrs[1];
    attrs[0].id = cudaLaunchAttributeProgrammaticStreamSerialization;
    attrs[0].val.programmaticStreamSerializationAllowed = 1;
    cfg.attrs = attrs;
    cfg.numAttrs = 1;
    cudaLaunchKernelEx(&cfg, lbs_kernel, vt, sk, la, out, V, B);
}